// round 2
// baseline (speedup 1.0000x reference)
#include <cuda_runtime.h>
#include <cstdint>

#define TE      128      // edges per CTA tile
#define NTHR    256
#define CINDIM  129      // 2F+1
#define HIDDIM  128
#define FDIM    64
#define HPAD    132      // padded row stride for s_h

// smem (floats): s_cmb[129][128] | s_h[128][132] | s_rel[3][128] | s_col[128]
#define SM_CMB_F   (CINDIM * TE)
#define SM_H_F     (HIDDIM * HPAD)
#define SM_REL_F   (3 * TE)
#define SM_COL_F   (TE)
#define SMEM_FLOATS (SM_CMB_F + SM_H_F + SM_REL_F + SM_COL_F)
#define SMEM_BYTES  (SMEM_FLOATS * 4)

static __device__ __forceinline__ float silu_f(float v) {
    return v * (1.0f / (1.0f + __expf(-v)));
}

extern "C" __global__ void __launch_bounds__(NTHR, 1)
emp_edge_kernel(const float* __restrict__ x,
                const float* __restrict__ pos,
                const int* __restrict__ ei,          // int32! (JAX x64 disabled)
                const float* __restrict__ W1x, const float* __restrict__ b1x,
                const float* __restrict__ W2x, const float* __restrict__ b2x,
                const float* __restrict__ W1p, const float* __restrict__ b1p,
                const float* __restrict__ W2p, const float* __restrict__ b2p,
                float* __restrict__ out_x, float* __restrict__ out_pos,
                int E)
{
    extern __shared__ float sm[];
    float* s_cmb = sm;                         // [129][TE]  k-major
    float* s_h   = sm + SM_CMB_F;              // [TE][HPAD] e-major (also reused as s_red)
    float* s_rel = s_h + SM_H_F;               // [3][TE]
    int*   s_col = (int*)(s_rel + SM_REL_F);   // [TE]

    const int t = threadIdx.x;
    const int e_base = blockIdx.x * TE;

    // ---------------- Phase A: gather combined features ----------------
    {
        const int el   = t >> 1;     // local edge 0..127
        const int half = t & 1;      // 0 -> x[row], 1 -> x[col]
        const int ge   = e_base + el;
        if (ge < E) {
            const int r = ei[ge];
            const int c = ei[E + ge];
            const int node = half ? c : r;
            const float4* xr = (const float4*)(x + (size_t)node * 64);
            #pragma unroll
            for (int i = 0; i < 16; i++) {
                float4 v = __ldg(xr + i);
                const int k0 = half * 64 + i * 4;
                s_cmb[(k0 + 0) * TE + el] = v.x;
                s_cmb[(k0 + 1) * TE + el] = v.y;
                s_cmb[(k0 + 2) * TE + el] = v.z;
                s_cmb[(k0 + 3) * TE + el] = v.w;
            }
            if (half == 0) {
                const float* pr = pos + (size_t)r * 3;
                const float* pc = pos + (size_t)c * 3;
                float rx = __ldg(pr + 0) - __ldg(pc + 0);
                float ry = __ldg(pr + 1) - __ldg(pc + 1);
                float rz = __ldg(pr + 2) - __ldg(pc + 2);
                s_rel[0 * TE + el] = rx;
                s_rel[1 * TE + el] = ry;
                s_rel[2 * TE + el] = rz;
                s_cmb[128 * TE + el] = rx * rx + ry * ry + rz * rz;
                s_col[el] = c;
            }
        } else {
            #pragma unroll
            for (int i = 0; i < 16; i++) {
                const int k0 = half * 64 + i * 4;
                s_cmb[(k0 + 0) * TE + el] = 0.f;
                s_cmb[(k0 + 1) * TE + el] = 0.f;
                s_cmb[(k0 + 2) * TE + el] = 0.f;
                s_cmb[(k0 + 3) * TE + el] = 0.f;
            }
            if (half == 0) {
                s_rel[0 * TE + el] = 0.f; s_rel[1 * TE + el] = 0.f; s_rel[2 * TE + el] = 0.f;
                s_cmb[128 * TE + el] = 0.f;
                s_col[el] = -1;
            }
        }
    }
    __syncthreads();

    // ---------------- Phase B: hidden = silu(combined @ W1x + b1x) ----------------
    {
        const int ty = t >> 4, tx = t & 15;
        const int e0 = ty * 8, j0 = tx * 8;
        float acc[8][8];
        {
            float4 bb0 = __ldg((const float4*)(b1x + j0));
            float4 bb1 = __ldg((const float4*)(b1x + j0 + 4));
            float binit[8] = {bb0.x, bb0.y, bb0.z, bb0.w, bb1.x, bb1.y, bb1.z, bb1.w};
            #pragma unroll
            for (int i = 0; i < 8; i++)
                #pragma unroll
                for (int u = 0; u < 8; u++) acc[i][u] = binit[u];
        }
        #pragma unroll 3
        for (int k = 0; k < CINDIM; k++) {
            float4 a0 = *(const float4*)(s_cmb + k * TE + e0);
            float4 a1 = *(const float4*)(s_cmb + k * TE + e0 + 4);
            float4 w0 = __ldg((const float4*)(W1x + k * HIDDIM + j0));
            float4 w1 = __ldg((const float4*)(W1x + k * HIDDIM + j0 + 4));
            float a[8] = {a0.x, a0.y, a0.z, a0.w, a1.x, a1.y, a1.z, a1.w};
            float w[8] = {w0.x, w0.y, w0.z, w0.w, w1.x, w1.y, w1.z, w1.w};
            #pragma unroll
            for (int i = 0; i < 8; i++)
                #pragma unroll
                for (int u = 0; u < 8; u++) acc[i][u] += a[i] * w[u];
        }
        #pragma unroll
        for (int i = 0; i < 8; i++) {
            float4 v0, v1;
            v0.x = silu_f(acc[i][0]); v0.y = silu_f(acc[i][1]);
            v0.z = silu_f(acc[i][2]); v0.w = silu_f(acc[i][3]);
            v1.x = silu_f(acc[i][4]); v1.y = silu_f(acc[i][5]);
            v1.z = silu_f(acc[i][6]); v1.w = silu_f(acc[i][7]);
            *(float4*)(s_h + (e0 + i) * HPAD + j0)     = v0;
            *(float4*)(s_h + (e0 + i) * HPAD + j0 + 4) = v1;
        }
    }
    __syncthreads();

    // ---------------- Phase C: msg = h @ W2x + b2x ; scatter-add ----------------
    {
        const int ey = t >> 3, fx = t & 7;     // ey 0..31, fx 0..7
        const int e0 = ey * 4, f0 = fx * 8;
        float acc2[4][8];
        {
            float4 b20 = __ldg((const float4*)(b2x + f0));
            float4 b21 = __ldg((const float4*)(b2x + f0 + 4));
            float binit[8] = {b20.x, b20.y, b20.z, b20.w, b21.x, b21.y, b21.z, b21.w};
            #pragma unroll
            for (int i = 0; i < 4; i++)
                #pragma unroll
                for (int u = 0; u < 8; u++) acc2[i][u] = binit[u];
        }
        #pragma unroll 4
        for (int j = 0; j < HIDDIM; j++) {
            float a0 = s_h[(e0 + 0) * HPAD + j];
            float a1 = s_h[(e0 + 1) * HPAD + j];
            float a2 = s_h[(e0 + 2) * HPAD + j];
            float a3 = s_h[(e0 + 3) * HPAD + j];
            float4 w0 = __ldg((const float4*)(W2x + j * FDIM + f0));
            float4 w1 = __ldg((const float4*)(W2x + j * FDIM + f0 + 4));
            float w[8] = {w0.x, w0.y, w0.z, w0.w, w1.x, w1.y, w1.z, w1.w};
            float a[4] = {a0, a1, a2, a3};
            #pragma unroll
            for (int i = 0; i < 4; i++)
                #pragma unroll
                for (int u = 0; u < 8; u++) acc2[i][u] += a[i] * w[u];
        }
        #pragma unroll
        for (int i = 0; i < 4; i++) {
            const int c = s_col[e0 + i];
            if (c >= 0) {
                float* dst = out_x + (size_t)c * FDIM + f0;
                #pragma unroll
                for (int u = 0; u < 8; u++) atomicAdd(dst + u, acc2[i][u]);
            }
        }
    }
    __syncthreads();   // all s_h reads done before reuse as reduction scratch

    // ---------------- Phase D: weight = silu(combined @ W1p + b1p) @ W2p + b2p ----------------
    {
        const int ty = t >> 4, tx = t & 15;
        const int e0 = ty * 8, j0 = tx * 8;
        float acc[8][8];
        {
            float4 bb0 = __ldg((const float4*)(b1p + j0));
            float4 bb1 = __ldg((const float4*)(b1p + j0 + 4));
            float binit[8] = {bb0.x, bb0.y, bb0.z, bb0.w, bb1.x, bb1.y, bb1.z, bb1.w};
            #pragma unroll
            for (int i = 0; i < 8; i++)
                #pragma unroll
                for (int u = 0; u < 8; u++) acc[i][u] = binit[u];
        }
        #pragma unroll 3
        for (int k = 0; k < CINDIM; k++) {
            float4 a0 = *(const float4*)(s_cmb + k * TE + e0);
            float4 a1 = *(const float4*)(s_cmb + k * TE + e0 + 4);
            float4 w0 = __ldg((const float4*)(W1p + k * HIDDIM + j0));
            float4 w1 = __ldg((const float4*)(W1p + k * HIDDIM + j0 + 4));
            float a[8] = {a0.x, a0.y, a0.z, a0.w, a1.x, a1.y, a1.z, a1.w};
            float w[8] = {w0.x, w0.y, w0.z, w0.w, w1.x, w1.y, w1.z, w1.w};
            #pragma unroll
            for (int i = 0; i < 8; i++)
                #pragma unroll
                for (int u = 0; u < 8; u++) acc[i][u] += a[i] * w[u];
        }
        // fold W2p within this thread's j-slice
        float4 wp0 = __ldg((const float4*)(W2p + j0));
        float4 wp1 = __ldg((const float4*)(W2p + j0 + 4));
        float wp[8] = {wp0.x, wp0.y, wp0.z, wp0.w, wp1.x, wp1.y, wp1.z, wp1.w};
        float* s_red = s_h;   // reuse, stride 17 to dodge bank conflicts
        #pragma unroll
        for (int i = 0; i < 8; i++) {
            float p = 0.f;
            #pragma unroll
            for (int u = 0; u < 8; u++) p += silu_f(acc[i][u]) * wp[u];
            s_red[(e0 + i) * 17 + tx] = p;
        }
    }
    __syncthreads();

    // reduce 16 partials per edge, scale rel_pos, scatter-add
    if (t < TE) {
        const int c = s_col[t];
        if (c >= 0) {
            const float* s_red = s_h;
            float w = __ldg(b2p);
            #pragma unroll
            for (int q = 0; q < 16; q++) w += s_red[t * 17 + q];
            atomicAdd(out_pos + (size_t)c * 3 + 0, w * s_rel[0 * TE + t]);
            atomicAdd(out_pos + (size_t)c * 3 + 1, w * s_rel[1 * TE + t]);
            atomicAdd(out_pos + (size_t)c * 3 + 2, w * s_rel[2 * TE + t]);
        }
    }
}

extern "C" void kernel_launch(void* const* d_in, const int* in_sizes, int n_in,
                              void* d_out, int out_size) {
    const float* x   = (const float*)d_in[0];
    const float* pos = (const float*)d_in[1];
    const int*   ei  = (const int*)d_in[2];      // int32 (JAX default: x64 disabled)
    const float* W1x = (const float*)d_in[3];
    const float* b1x = (const float*)d_in[4];
    const float* W2x = (const float*)d_in[5];
    const float* b2x = (const float*)d_in[6];
    const float* W1p = (const float*)d_in[7];
    const float* b1p = (const float*)d_in[8];
    const float* W2p = (const float*)d_in[9];
    const float* b2p = (const float*)d_in[10];

    const int N = in_sizes[0] / FDIM;       // nodes
    const int E = in_sizes[2] / 2;          // edges

    float* out     = (float*)d_out;
    float* out_x   = out;                    // [N, 64]
    float* out_pos = out + (size_t)N * FDIM; // [N, 3]

    cudaMemsetAsync(d_out, 0, (size_t)out_size * sizeof(float), 0);

    cudaFuncSetAttribute(emp_edge_kernel,
                         cudaFuncAttributeMaxDynamicSharedMemorySize, SMEM_BYTES);

    const int nblk = (E + TE - 1) / TE;
    emp_edge_kernel<<<nblk, NTHR, SMEM_BYTES>>>(
        x, pos, ei, W1x, b1x, W2x, b2x, W1p, b1p, W2p, b2p, out_x, out_pos, E);
}

// round 6
// speedup vs baseline: 2.6791x; 2.6791x over previous
#include <cuda_runtime.h>
#include <cstdint>

#define NTHR  256
#define NGRID 148
#define MT    64          // edges per tile
#define PAD   132         // padded row stride (floats) -> conflict-free fragments
#define FDIM  64
#define HID   128

// ---- smem layout (float offsets) ----
#define S_A    0                       // 64 x 132   A tile (tf32 bits), reused as h
#define S_W1X  8448                    // 128 x 132  W1x^T [n][k] tf32
#define S_W1P  25344                   // 128 x 132  W1p^T
#define S_W2X  42240                   // 64 x 132   W2x^T [f][j]
#define S_B1X  50688                   // 128 fp32
#define S_B1P  50816
#define S_W1XL 50944                   // W1x row 128 (dist^2) fp32
#define S_W1PL 51072
#define S_W2P  51200                   // 128 fp32
#define S_B2X  51328                   // 64
#define S_DIST 51392                   // 64
#define S_REL  51456                   // 3 x 64
#define S_WACC 51648                   // 4 x 64
#define S_COL  51904                   // 64 (int)
#define S_TOT  51968
#define SMEM_BYTES (S_TOT * 4)

__device__ __forceinline__ uint32_t tf32(float f) {
    uint32_t u; asm("cvt.rna.tf32.f32 %0, %1;" : "=r"(u) : "f"(f)); return u;
}
static __device__ __forceinline__ float silu_f(float v) {
    return v * (1.0f / (1.0f + __expf(-v)));
}
__device__ __forceinline__ void mma8(float* c, const uint32_t* a, const uint32_t* b) {
    asm volatile("mma.sync.aligned.m16n8k8.row.col.f32.tf32.tf32.f32 "
        "{%0,%1,%2,%3}, {%4,%5,%6,%7}, {%8,%9}, {%0,%1,%2,%3};"
        : "+f"(c[0]), "+f"(c[1]), "+f"(c[2]), "+f"(c[3])
        : "r"(a[0]), "r"(a[1]), "r"(a[2]), "r"(a[3]), "r"(b[0]), "r"(b[1]));
}

extern "C" __global__ void __launch_bounds__(NTHR, 1)
emp_mma_kernel(const float* __restrict__ x,
               const float* __restrict__ pos,
               const int* __restrict__ ei,
               const float* __restrict__ W1x, const float* __restrict__ b1x,
               const float* __restrict__ W2x, const float* __restrict__ b2x,
               const float* __restrict__ W1p, const float* __restrict__ b1p,
               const float* __restrict__ W2p, const float* __restrict__ b2p,
               float* __restrict__ out_x, float* __restrict__ out_pos,
               int E)
{
    extern __shared__ float sm[];
    uint32_t* smu = (uint32_t*)sm;
    int* scol = (int*)(sm + S_COL);

    const int t = threadIdx.x;
    const int lane = t & 31, wid = t >> 5;
    const int qr = lane >> 2, qc = lane & 3;

    // ---- one-time weight staging (transposed, tf32-rounded, pad-132) ----
    for (int idx = t; idx < HID * HID; idx += NTHR) {      // W1x^T, W1p^T: [n][k]
        int k = idx >> 7, n = idx & 127;
        smu[S_W1X + n * PAD + k] = tf32(W1x[idx]);
        smu[S_W1P + n * PAD + k] = tf32(W1p[idx]);
    }
    for (int idx = t; idx < HID * FDIM; idx += NTHR) {     // W2x^T: [f][j]
        int j = idx >> 6, f = idx & 63;
        smu[S_W2X + f * PAD + j] = tf32(W2x[idx]);
    }
    if (t < HID) {
        sm[S_B1X + t]  = b1x[t];
        sm[S_B1P + t]  = b1p[t];
        sm[S_W1XL + t] = W1x[HID * HID + t];   // dist^2 row of W1x
        sm[S_W1PL + t] = W1p[HID * HID + t];
        sm[S_W2P + t]  = W2p[t];
    }
    if (t < FDIM) sm[S_B2X + t] = b2x[t];
    const float b2p0 = __ldg(b2p);
    __syncthreads();

    const int ntiles = (E + MT - 1) / MT;

    for (int tile = blockIdx.x; tile < ntiles; tile += gridDim.x) {
        // ---------------- gather ----------------
        const int e  = t & 63;          // local edge
        const int kb = t >> 6;          // k-block 0..3 (32 feats each)
        const int ge = tile * MT + e;

        if (kb == 0) {
            if (ge < E) {
                int r = ei[ge], c = ei[E + ge];
                float rx = __ldg(pos + (size_t)r * 3 + 0) - __ldg(pos + (size_t)c * 3 + 0);
                float ry = __ldg(pos + (size_t)r * 3 + 1) - __ldg(pos + (size_t)c * 3 + 1);
                float rz = __ldg(pos + (size_t)r * 3 + 2) - __ldg(pos + (size_t)c * 3 + 2);
                sm[S_REL + e] = rx; sm[S_REL + 64 + e] = ry; sm[S_REL + 128 + e] = rz;
                sm[S_DIST + e] = rx * rx + ry * ry + rz * rz;
                scol[e] = c;
            } else {
                sm[S_REL + e] = 0.f; sm[S_REL + 64 + e] = 0.f; sm[S_REL + 128 + e] = 0.f;
                sm[S_DIST + e] = 0.f;
                scol[e] = -1;
            }
        }
        {
            uint32_t* dst = smu + S_A + e * PAD + kb * 32;
            if (ge < E) {
                const int node = ei[(kb < 2 ? 0 : E) + ge];
                const float4* src = (const float4*)(x + (size_t)node * 64 + (kb & 1) * 32);
                #pragma unroll
                for (int i = 0; i < 8; i++) {
                    float4 v = __ldg(src + i);
                    uint4 u = make_uint4(tf32(v.x), tf32(v.y), tf32(v.z), tf32(v.w));
                    *(uint4*)(dst + i * 4) = u;
                }
            } else {
                #pragma unroll
                for (int i = 0; i < 8; i++) *(uint4*)(dst + i * 4) = make_uint4(0, 0, 0, 0);
            }
        }
        __syncthreads();

        // ---------------- GEMM1: combined @ {W1x, W1p} ----------------
        const int g  = wid >> 2;   // 0: phi_x warps, 1: phi_p warps
        const int ws = wid & 3;    // n-slice: cols [32*ws, 32*ws+32)
        float acc[4][4][4];
        #pragma unroll
        for (int m = 0; m < 4; m++)
            #pragma unroll
            for (int n = 0; n < 4; n++)
                #pragma unroll
                for (int c = 0; c < 4; c++) acc[m][n][c] = 0.f;

        {
            const uint32_t* Ab = smu + S_A + qr * PAD + qc;
            const uint32_t* Wb = smu + (g ? S_W1P : S_W1X) + (ws * 32 + qr) * PAD + qc;
            #pragma unroll
            for (int k0 = 0; k0 < 128; k0 += 8) {
                uint32_t a[4][4];
                #pragma unroll
                for (int m = 0; m < 4; m++) {
                    const uint32_t* p = Ab + m * 16 * PAD + k0;
                    a[m][0] = p[0]; a[m][1] = p[8 * PAD]; a[m][2] = p[4]; a[m][3] = p[8 * PAD + 4];
                }
                uint32_t b[4][2];
                #pragma unroll
                for (int n = 0; n < 4; n++) {
                    const uint32_t* p = Wb + n * 8 * PAD + k0;
                    b[n][0] = p[0]; b[n][1] = p[4];
                }
                #pragma unroll
                for (int m = 0; m < 4; m++)
                    #pragma unroll
                    for (int n = 0; n < 4; n++) mma8(acc[m][n], a[m], b[n]);
            }
        }
        __syncthreads();   // all A-tile reads done before h overwrites it

        // ---------------- epilogue 1 ----------------
        float dd0[4], dd1[4];
        #pragma unroll
        for (int m = 0; m < 4; m++) {
            dd0[m] = sm[S_DIST + m * 16 + qr];
            dd1[m] = sm[S_DIST + m * 16 + qr + 8];
        }
        if (g == 0) {
            // h = silu(acc + b1x + dist*w1xL) -> back into S_A (tf32)
            #pragma unroll
            for (int n = 0; n < 4; n++) {
                const int j0 = ws * 32 + n * 8 + 2 * qc;
                const float bj0 = sm[S_B1X + j0],  bj1 = sm[S_B1X + j0 + 1];
                const float lj0 = sm[S_W1XL + j0], lj1 = sm[S_W1XL + j0 + 1];
                #pragma unroll
                for (int m = 0; m < 4; m++) {
                    const int r0 = m * 16 + qr;
                    float h00 = silu_f(acc[m][n][0] + bj0 + dd0[m] * lj0);
                    float h01 = silu_f(acc[m][n][1] + bj1 + dd0[m] * lj1);
                    float h10 = silu_f(acc[m][n][2] + bj0 + dd1[m] * lj0);
                    float h11 = silu_f(acc[m][n][3] + bj1 + dd1[m] * lj1);
                    *(uint2*)(smu + S_A + r0 * PAD + j0)       = make_uint2(tf32(h00), tf32(h01));
                    *(uint2*)(smu + S_A + (r0 + 8) * PAD + j0) = make_uint2(tf32(h10), tf32(h11));
                }
            }
        } else {
            // fold phi_p: wpart = sum_j silu(acc + b1p + dist*w1pL) * W2p[j]
            #pragma unroll
            for (int m = 0; m < 4; m++) {
                float pr0 = 0.f, pr1 = 0.f;
                #pragma unroll
                for (int n = 0; n < 4; n++) {
                    const int j0 = ws * 32 + n * 8 + 2 * qc;
                    const float bj0 = sm[S_B1P + j0],  bj1 = sm[S_B1P + j0 + 1];
                    const float lj0 = sm[S_W1PL + j0], lj1 = sm[S_W1PL + j0 + 1];
                    const float w0  = sm[S_W2P + j0],  w1  = sm[S_W2P + j0 + 1];
                    pr0 += silu_f(acc[m][n][0] + bj0 + dd0[m] * lj0) * w0
                         + silu_f(acc[m][n][1] + bj1 + dd0[m] * lj1) * w1;
                    pr1 += silu_f(acc[m][n][2] + bj0 + dd1[m] * lj0) * w0
                         + silu_f(acc[m][n][3] + bj1 + dd1[m] * lj1) * w1;
                }
                pr0 += __shfl_xor_sync(0xffffffff, pr0, 1);
                pr0 += __shfl_xor_sync(0xffffffff, pr0, 2);
                pr1 += __shfl_xor_sync(0xffffffff, pr1, 1);
                pr1 += __shfl_xor_sync(0xffffffff, pr1, 2);
                if (qc == 0) {
                    sm[S_WACC + ws * 64 + m * 16 + qr]     = pr0;
                    sm[S_WACC + ws * 64 + m * 16 + qr + 8] = pr1;
                }
            }
        }
        __syncthreads();

        // ---------------- pos scatter ----------------
        if (t < 64) {
            const int c = scol[t];
            if (c >= 0) {
                float w = b2p0 + sm[S_WACC + t] + sm[S_WACC + 64 + t]
                               + sm[S_WACC + 128 + t] + sm[S_WACC + 192 + t];
                float px = w * sm[S_REL + t];
                float py = w * sm[S_REL + 64 + t];
                float pz = w * sm[S_REL + 128 + t];
                float* dp = out_pos + (size_t)c * 3;
                asm volatile("red.global.add.f32 [%0], %1;" :: "l"(dp + 0), "f"(px) : "memory");
                asm volatile("red.global.add.f32 [%0], %1;" :: "l"(dp + 1), "f"(py) : "memory");
                asm volatile("red.global.add.f32 [%0], %1;" :: "l"(dp + 2), "f"(pz) : "memory");
            }
        }

        // ---------------- GEMM2: h @ W2x ----------------
        {
            const int m2  = wid & 3;     // m-tile
            const int nb2 = wid >> 2;    // n-slice: cols [32*nb2, 32*nb2+32)
            float acc2[4][4];
            #pragma unroll
            for (int n = 0; n < 4; n++)
                #pragma unroll
                for (int c = 0; c < 4; c++) acc2[n][c] = 0.f;

            const uint32_t* Ab = smu + S_A + (m2 * 16 + qr) * PAD + qc;
            const uint32_t* Wb = smu + S_W2X + (nb2 * 32 + qr) * PAD + qc;
            #pragma unroll
            for (int k0 = 0; k0 < 128; k0 += 8) {
                uint32_t a[4];
                a[0] = Ab[k0]; a[1] = Ab[8 * PAD + k0]; a[2] = Ab[k0 + 4]; a[3] = Ab[8 * PAD + k0 + 4];
                #pragma unroll
                for (int n = 0; n < 4; n++) {
                    uint32_t b[2];
                    const uint32_t* p = Wb + n * 8 * PAD + k0;
                    b[0] = p[0]; b[1] = p[4];
                    mma8(acc2[n], a, b);
                }
            }

            // epilogue 2: + b2x, vectorized scatter-add
            const int r0 = m2 * 16 + qr;
            const int c0 = scol[r0];
            const int c1 = scol[r0 + 8];
            #pragma unroll
            for (int n = 0; n < 4; n++) {
                const int f0 = nb2 * 32 + n * 8 + 2 * qc;
                const float b20 = sm[S_B2X + f0], b21 = sm[S_B2X + f0 + 1];
                if (c0 >= 0) {
                    float v0 = acc2[n][0] + b20, v1 = acc2[n][1] + b21;
                    asm volatile("red.global.add.v2.f32 [%0], {%1, %2};"
                                 :: "l"(out_x + (size_t)c0 * 64 + f0), "f"(v0), "f"(v1) : "memory");
                }
                if (c1 >= 0) {
                    float v0 = acc2[n][2] + b20, v1 = acc2[n][3] + b21;
                    asm volatile("red.global.add.v2.f32 [%0], {%1, %2};"
                                 :: "l"(out_x + (size_t)c1 * 64 + f0), "f"(v0), "f"(v1) : "memory");
                }
            }
        }
        __syncthreads();   // protect S_A / S_WACC / S_COL before next tile's gather
    }
}

extern "C" void kernel_launch(void* const* d_in, const int* in_sizes, int n_in,
                              void* d_out, int out_size) {
    const float* x   = (const float*)d_in[0];
    const float* pos = (const float*)d_in[1];
    const int*   ei  = (const int*)d_in[2];
    const float* W1x = (const float*)d_in[3];
    const float* b1x = (const float*)d_in[4];
    const float* W2x = (const float*)d_in[5];
    const float* b2x = (const float*)d_in[6];
    const float* W1p = (const float*)d_in[7];
    const float* b1p = (const float*)d_in[8];
    const float* W2p = (const float*)d_in[9];
    const float* b2p = (const float*)d_in[10];

    const int N = in_sizes[0] / FDIM;
    const int E = in_sizes[2] / 2;

    float* out     = (float*)d_out;
    float* out_x   = out;
    float* out_pos = out + (size_t)N * FDIM;

    cudaMemsetAsync(d_out, 0, (size_t)out_size * sizeof(float), 0);

    cudaFuncSetAttribute(emp_mma_kernel,
                         cudaFuncAttributeMaxDynamicSharedMemorySize, SMEM_BYTES);

    emp_mma_kernel<<<NGRID, NTHR, SMEM_BYTES>>>(
        x, pos, ei, W1x, b1x, W2x, b2x, W1p, b1p, W2p, b2p, out_x, out_pos, E);
}

// round 8
// speedup vs baseline: 2.9485x; 1.1006x over previous
#include <cuda_runtime.h>
#include <cstdint>

#define NTHR  512
#define NGRID 148
#define MT    64          // edges per tile
#define PAD   132         // padded row stride (floats) -> conflict-free fragments
#define FDIM  64
#define HID   128

// ---- smem layout (float offsets) ----
#define S_A    0                       // 64 x 132   A tile (tf32 bits), reused as h
#define S_W1X  8448                    // 128 x 132  W1x^T [n][k] tf32
#define S_W1P  25344                   // 128 x 132  W1p^T
#define S_W2X  42240                   // 64 x 132   W2x^T [f][j]
#define S_B1X  50688                   // 128 fp32
#define S_B1P  50816
#define S_W1XL 50944                   // W1x row 128 (dist^2) fp32
#define S_W1PL 51072
#define S_W2P  51200                   // 128 fp32
#define S_B2X  51328                   // 64
#define S_DIST 51392                   // 64
#define S_REL  51456                   // 3 x 64
#define S_WACC 51648                   // 8 x 64
#define S_COL  52160                   // 64 (int)
#define S_TOT  52224
#define SMEM_BYTES (S_TOT * 4)

__device__ __forceinline__ uint32_t tf32(float f) {
    uint32_t u; asm("cvt.rna.tf32.f32 %0, %1;" : "=r"(u) : "f"(f)); return u;
}
static __device__ __forceinline__ float silu_f(float v) {
    return v * (1.0f / (1.0f + __expf(-v)));
}
__device__ __forceinline__ void mma8(float* c, const uint32_t* a, const uint32_t* b) {
    asm volatile("mma.sync.aligned.m16n8k8.row.col.f32.tf32.tf32.f32 "
        "{%0,%1,%2,%3}, {%4,%5,%6,%7}, {%8,%9}, {%0,%1,%2,%3};"
        : "+f"(c[0]), "+f"(c[1]), "+f"(c[2]), "+f"(c[3])
        : "r"(a[0]), "r"(a[1]), "r"(a[2]), "r"(a[3]), "r"(b[0]), "r"(b[1]));
}

extern "C" __global__ void __launch_bounds__(NTHR, 1)
emp_mma_kernel(const float* __restrict__ x,
               const float* __restrict__ pos,
               const int* __restrict__ ei,
               const float* __restrict__ W1x, const float* __restrict__ b1x,
               const float* __restrict__ W2x, const float* __restrict__ b2x,
               const float* __restrict__ W1p, const float* __restrict__ b1p,
               const float* __restrict__ W2p, const float* __restrict__ b2p,
               float* __restrict__ out_x, float* __restrict__ out_pos,
               int E)
{
    extern __shared__ float sm[];
    uint32_t* smu = (uint32_t*)sm;
    int* scol = (int*)(sm + S_COL);

    const int t = threadIdx.x;
    const int lane = t & 31, wid = t >> 5;
    const int qr = lane >> 2, qc = lane & 3;

    // ---- one-time weight staging (transposed, tf32-rounded, pad-132) ----
    for (int idx = t; idx < HID * HID; idx += NTHR) {      // W1x^T, W1p^T: [n][k]
        int k = idx >> 7, n = idx & 127;
        smu[S_W1X + n * PAD + k] = tf32(W1x[idx]);
        smu[S_W1P + n * PAD + k] = tf32(W1p[idx]);
    }
    for (int idx = t; idx < HID * FDIM; idx += NTHR) {     // W2x^T: [f][j]
        int j = idx >> 6, f = idx & 63;
        smu[S_W2X + f * PAD + j] = tf32(W2x[idx]);
    }
    if (t < HID) {
        sm[S_B1X + t]  = b1x[t];
        sm[S_B1P + t]  = b1p[t];
        sm[S_W1XL + t] = W1x[HID * HID + t];   // dist^2 row of W1x
        sm[S_W1PL + t] = W1p[HID * HID + t];
        sm[S_W2P + t]  = W2p[t];
    }
    if (t < FDIM) sm[S_B2X + t] = b2x[t];
    const float b2p0 = __ldg(b2p);
    __syncthreads();

    const int ntiles = (E + MT - 1) / MT;

    for (int tile = blockIdx.x; tile < ntiles; tile += gridDim.x) {
        // ---------------- gather (8 k-blocks of 16 feats) ----------------
        const int e  = t & 63;          // local edge
        const int kb = t >> 6;          // k-block 0..7
        const int ge = tile * MT + e;

        if (kb == 0) {
            if (ge < E) {
                int r = ei[ge], c = ei[E + ge];
                float rx = __ldg(pos + (size_t)r * 3 + 0) - __ldg(pos + (size_t)c * 3 + 0);
                float ry = __ldg(pos + (size_t)r * 3 + 1) - __ldg(pos + (size_t)c * 3 + 1);
                float rz = __ldg(pos + (size_t)r * 3 + 2) - __ldg(pos + (size_t)c * 3 + 2);
                sm[S_REL + e] = rx; sm[S_REL + 64 + e] = ry; sm[S_REL + 128 + e] = rz;
                sm[S_DIST + e] = rx * rx + ry * ry + rz * rz;
                scol[e] = c;
            } else {
                sm[S_REL + e] = 0.f; sm[S_REL + 64 + e] = 0.f; sm[S_REL + 128 + e] = 0.f;
                sm[S_DIST + e] = 0.f;
                scol[e] = -1;
            }
        }
        {
            uint32_t* dst = smu + S_A + e * PAD + kb * 16;
            if (ge < E) {
                const int node = ei[(kb < 4 ? 0 : E) + ge];
                const float4* src = (const float4*)(x + (size_t)node * 64 + (kb & 3) * 16);
                #pragma unroll
                for (int i = 0; i < 4; i++) {
                    float4 v = __ldg(src + i);
                    *(uint4*)(dst + i * 4) = make_uint4(tf32(v.x), tf32(v.y), tf32(v.z), tf32(v.w));
                }
            } else {
                #pragma unroll
                for (int i = 0; i < 4; i++) *(uint4*)(dst + i * 4) = make_uint4(0, 0, 0, 0);
            }
        }
        __syncthreads();

        // ---------------- GEMM1: combined @ {W1x, W1p} ----------------
        const int g  = wid >> 3;   // 0: phi_x warps (0-7), 1: phi_p warps (8-15)
        const int ws = wid & 7;    // n-slice: cols [16*ws, 16*ws+16)
        float acc[4][2][4];
        #pragma unroll
        for (int m = 0; m < 4; m++)
            #pragma unroll
            for (int n = 0; n < 2; n++)
                #pragma unroll
                for (int c = 0; c < 4; c++) acc[m][n][c] = 0.f;

        {
            const uint32_t* Ab = smu + S_A + qr * PAD + qc;
            const uint32_t* Wb = smu + (g ? S_W1P : S_W1X) + (ws * 16 + qr) * PAD + qc;
            #pragma unroll
            for (int k0 = 0; k0 < 128; k0 += 8) {
                uint32_t a[4][4];
                #pragma unroll
                for (int m = 0; m < 4; m++) {
                    const uint32_t* p = Ab + m * 16 * PAD + k0;
                    a[m][0] = p[0]; a[m][1] = p[8 * PAD]; a[m][2] = p[4]; a[m][3] = p[8 * PAD + 4];
                }
                uint32_t b[2][2];
                #pragma unroll
                for (int n = 0; n < 2; n++) {
                    const uint32_t* p = Wb + n * 8 * PAD + k0;
                    b[n][0] = p[0]; b[n][1] = p[4];
                }
                #pragma unroll
                for (int m = 0; m < 4; m++)
                    #pragma unroll
                    for (int n = 0; n < 2; n++) mma8(acc[m][n], a[m], b[n]);
            }
        }
        __syncthreads();   // all A-tile reads done before h overwrites it

        // ---------------- epilogue 1 ----------------
        float dd0[4], dd1[4];
        #pragma unroll
        for (int m = 0; m < 4; m++) {
            dd0[m] = sm[S_DIST + m * 16 + qr];
            dd1[m] = sm[S_DIST + m * 16 + qr + 8];
        }
        if (g == 0) {
            // h = silu(acc + b1x + dist*w1xL) -> back into S_A (tf32)
            #pragma unroll
            for (int n = 0; n < 2; n++) {
                const int j0 = ws * 16 + n * 8 + 2 * qc;
                const float bj0 = sm[S_B1X + j0],  bj1 = sm[S_B1X + j0 + 1];
                const float lj0 = sm[S_W1XL + j0], lj1 = sm[S_W1XL + j0 + 1];
                #pragma unroll
                for (int m = 0; m < 4; m++) {
                    const int r0 = m * 16 + qr;
                    float h00 = silu_f(acc[m][n][0] + bj0 + dd0[m] * lj0);
                    float h01 = silu_f(acc[m][n][1] + bj1 + dd0[m] * lj1);
                    float h10 = silu_f(acc[m][n][2] + bj0 + dd1[m] * lj0);
                    float h11 = silu_f(acc[m][n][3] + bj1 + dd1[m] * lj1);
                    *(uint2*)(smu + S_A + r0 * PAD + j0)       = make_uint2(tf32(h00), tf32(h01));
                    *(uint2*)(smu + S_A + (r0 + 8) * PAD + j0) = make_uint2(tf32(h10), tf32(h11));
                }
            }
        } else {
            // fold phi_p: wpart = sum_j silu(acc + b1p + dist*w1pL) * W2p[j]
            #pragma unroll
            for (int m = 0; m < 4; m++) {
                float pr0 = 0.f, pr1 = 0.f;
                #pragma unroll
                for (int n = 0; n < 2; n++) {
                    const int j0 = ws * 16 + n * 8 + 2 * qc;
                    const float bj0 = sm[S_B1P + j0],  bj1 = sm[S_B1P + j0 + 1];
                    const float lj0 = sm[S_W1PL + j0], lj1 = sm[S_W1PL + j0 + 1];
                    const float w0  = sm[S_W2P + j0],  w1  = sm[S_W2P + j0 + 1];
                    pr0 += silu_f(acc[m][n][0] + bj0 + dd0[m] * lj0) * w0
                         + silu_f(acc[m][n][1] + bj1 + dd0[m] * lj1) * w1;
                    pr1 += silu_f(acc[m][n][2] + bj0 + dd1[m] * lj0) * w0
                         + silu_f(acc[m][n][3] + bj1 + dd1[m] * lj1) * w1;
                }
                pr0 += __shfl_xor_sync(0xffffffff, pr0, 1);
                pr0 += __shfl_xor_sync(0xffffffff, pr0, 2);
                pr1 += __shfl_xor_sync(0xffffffff, pr1, 1);
                pr1 += __shfl_xor_sync(0xffffffff, pr1, 2);
                if (qc == 0) {
                    sm[S_WACC + ws * 64 + m * 16 + qr]     = pr0;
                    sm[S_WACC + ws * 64 + m * 16 + qr + 8] = pr1;
                }
            }
        }
        __syncthreads();

        // ---------------- pos scatter ----------------
        if (t < 64) {
            const int c = scol[t];
            if (c >= 0) {
                float w = b2p0;
                #pragma unroll
                for (int q = 0; q < 8; q++) w += sm[S_WACC + q * 64 + t];
                float px = w * sm[S_REL + t];
                float py = w * sm[S_REL + 64 + t];
                float pz = w * sm[S_REL + 128 + t];
                float* dp = out_pos + (size_t)c * 3;
                asm volatile("red.global.add.f32 [%0], %1;" :: "l"(dp + 0), "f"(px) : "memory");
                asm volatile("red.global.add.f32 [%0], %1;" :: "l"(dp + 1), "f"(py) : "memory");
                asm volatile("red.global.add.f32 [%0], %1;" :: "l"(dp + 2), "f"(pz) : "memory");
            }
        }

        // ---------------- GEMM2: h @ W2x ----------------
        {
            const int m2  = wid & 3;     // m-tile (16 edges)
            const int nb2 = wid >> 2;    // n-slice: cols [16*nb2, 16*nb2+16)
            float acc2[2][4];
            #pragma unroll
            for (int n = 0; n < 2; n++)
                #pragma unroll
                for (int c = 0; c < 4; c++) acc2[n][c] = 0.f;

            const uint32_t* Ab = smu + S_A + (m2 * 16 + qr) * PAD + qc;
            const uint32_t* Wb = smu + S_W2X + (nb2 * 16 + qr) * PAD + qc;
            #pragma unroll
            for (int k0 = 0; k0 < 128; k0 += 8) {
                uint32_t a[4];
                a[0] = Ab[k0]; a[1] = Ab[8 * PAD + k0]; a[2] = Ab[k0 + 4]; a[3] = Ab[8 * PAD + k0 + 4];
                #pragma unroll
                for (int n = 0; n < 2; n++) {
                    uint32_t b[2];
                    const uint32_t* p = Wb + n * 8 * PAD + k0;
                    b[0] = p[0]; b[1] = p[4];
                    mma8(acc2[n], a, b);
                }
            }

            // epilogue 2: + b2x, vectorized scatter-add
            const int r0 = m2 * 16 + qr;
            const int c0 = scol[r0];
            const int c1 = scol[r0 + 8];
            #pragma unroll
            for (int n = 0; n < 2; n++) {
                const int f0 = nb2 * 16 + n * 8 + 2 * qc;
                const float b20 = sm[S_B2X + f0], b21 = sm[S_B2X + f0 + 1];
                if (c0 >= 0) {
                    float v0 = acc2[n][0] + b20, v1 = acc2[n][1] + b21;
                    asm volatile("red.global.add.v2.f32 [%0], {%1, %2};"
                                 :: "l"(out_x + (size_t)c0 * 64 + f0), "f"(v0), "f"(v1) : "memory");
                }
                if (c1 >= 0) {
                    float v0 = acc2[n][2] + b20, v1 = acc2[n][3] + b21;
                    asm volatile("red.global.add.v2.f32 [%0], {%1, %2};"
                                 :: "l"(out_x + (size_t)c1 * 64 + f0), "f"(v0), "f"(v1) : "memory");
                }
            }
        }
        __syncthreads();   // protect S_A / S_WACC / S_COL before next tile's gather
    }
}

extern "C" void kernel_launch(void* const* d_in, const int* in_sizes, int n_in,
                              void* d_out, int out_size) {
    const float* x   = (const float*)d_in[0];
    const float* pos = (const float*)d_in[1];
    const int*   ei  = (const int*)d_in[2];
    const float* W1x = (const float*)d_in[3];
    const float* b1x = (const float*)d_in[4];
    const float* W2x = (const float*)d_in[5];
    const float* b2x = (const float*)d_in[6];
    const float* W1p = (const float*)d_in[7];
    const float* b1p = (const float*)d_in[8];
    const float* W2p = (const float*)d_in[9];
    const float* b2p = (const float*)d_in[10];

    const int N = in_sizes[0] / FDIM;
    const int E = in_sizes[2] / 2;

    float* out     = (float*)d_out;
    float* out_x   = out;
    float* out_pos = out + (size_t)N * FDIM;

    cudaMemsetAsync(d_out, 0, (size_t)out_size * sizeof(float), 0);

    cudaFuncSetAttribute(emp_mma_kernel,
                         cudaFuncAttributeMaxDynamicSharedMemorySize, SMEM_BYTES);

    emp_mma_kernel<<<NGRID, NTHR, SMEM_BYTES>>>(
        x, pos, ei, W1x, b1x, W2x, b2x, W1p, b1p, W2p, b2p, out_x, out_pos, E);
}